// round 6
// baseline (speedup 1.0000x reference)
#include <cuda_runtime.h>
#include <math.h>

#define LLEAF 2048
#define NNODES 4095
#define MEM 150
#define IN_DIM 300
#define HIDD 50
#define NCLS 5
#define HSTR 152
#define NTHR 480

typedef unsigned long long ull;

// Scratch (device globals: no allocations allowed)
__device__ float g_C[2][NNODES][HSTR];
__device__ float g_H[2][NNODES][HSTR];
__device__ float g_s[2][NNODES];
__device__ float g_red4[4];             // maxl, invsuml, maxr, invsumr
__device__ float g_part[2][32][HSTR];   // partial attention sums (deterministic)
__device__ unsigned g_gen;              // grid barrier generation (self-resetting)
__device__ unsigned g_cnt;              // grid barrier arrival count

__device__ __forceinline__ float sigf(float x) { return 1.f / (1.f + expf(-x)); }

__device__ __forceinline__ ull pack2(float a, float b) {
    ull r; asm("mov.b64 %0, {%1,%2};" : "=l"(r) : "f"(a), "f"(b)); return r;
}
__device__ __forceinline__ void ffma2(ull& d, ull a, ull b) {
    asm("fma.rn.f32x2 %0, %1, %2, %0;" : "+l"(d) : "l"(a), "l"(b));
}
__device__ __forceinline__ float2 unpack2(ull v) {
    float2 f; asm("mov.b64 {%0,%1}, %2;" : "=f"(f.x), "=f"(f.y) : "l"(v)); return f;
}

__device__ __forceinline__ unsigned ld_acq(unsigned* p) {
    unsigned v; asm volatile("ld.acquire.gpu.u32 %0, [%1];" : "=r"(v) : "l"(p) : "memory"); return v;
}
__device__ __forceinline__ void st_rel(unsigned* p, unsigned v) {
    asm volatile("st.release.gpu.u32 [%0], %1;" :: "l"(p), "r"(v) : "memory");
}

// Sense-reversing grid barrier (self-resetting; monotone generation).
__device__ __forceinline__ void gbar() {
    __syncthreads();
    if (threadIdx.x == 0) {
        unsigned gen = ld_acq(&g_gen);
        __threadfence();
        if (atomicAdd(&g_cnt, 1u) == gridDim.x - 1u) {
            g_cnt = 0u;
            st_rel(&g_gen, gen + 1u);
        } else {
            while (ld_acq(&g_gen) == gen) __nanosleep(64);
        }
    }
    __syncthreads();
}

// Group-scoped barrier: group grp = threads [160*grp, 160*grp+160), 5 warps.
__device__ __forceinline__ void gsync(int grp) {
    asm volatile("bar.sync %0, %1;" :: "r"(grp + 1), "r"(160) : "memory");
}

// ---------------------------------------------------------------------------
// Dynamic shared memory union
// ---------------------------------------------------------------------------
struct LvlG {                            // group-independent level task, R=8
    float ss[MEM][10], sl[MEM][10], sr[MEM][10];
    int li[8], ri[8], tt[8], kk[8];
};
struct LeafG {                           // group-independent leaf task, 16 leaves
    float xs[IN_DIM][18];
    int toks[16];
};
struct LvlSK {                           // whole-block split-K level task, R<=4
    float ss[MEM][6], sl[MEM][6], sr[MEM][6];
    float2 buf[2][MEM][2];
    int li[4], ri[4], tt[4], kk[4];
};
struct AttS { float w[3][128]; };
struct FinS {
    float q0[HSTR], q1[HSTR], beta[HSTR], alpha[HSTR];
    float slh[HSTR], srh[HSTR], hid[64], lg[8];
    float red[16]; float bc;
};
union SmemU {
    LvlG lvlg[3];
    LeafG leafg[3];
    LvlSK lvlsk;
    AttS att;
    FinS fin;
};

// ---------------------------------------------------------------------------
// Group-independent leaf task: 16 leaves, K=300, double-buffered weights.
// ---------------------------------------------------------------------------
__device__ __forceinline__ void leaf_task_g(
    LeafG& s, int task, int grp, int j,
    const int* __restrict__ ltok, const int* __restrict__ rtok,
    const float* __restrict__ emb, const float* __restrict__ Wx,
    const float* __restrict__ bx, const float* __restrict__ bh)
{
    const int t = task >> 7;
    const int g = task & 127;
    const int leaf0 = g * 16;
    const int* tok = t ? rtok : ltok;

    if (j < 16) s.toks[j] = tok[leaf0 + j];
    gsync(grp);
    for (int idx = j; idx < 16 * IN_DIM; idx += 160) {
        int r = idx / IN_DIM, k = idx - r * IN_DIM;
        s.xs[k][r] = emb[s.toks[r] * IN_DIM + k];
    }
    gsync(grp);

    if (j < MEM) {
        ull acc[24];
#pragma unroll
        for (int a = 0; a < 24; a++) acc[a] = 0ull;
        float wb[2][5][3];
#pragma unroll
        for (int q = 0; q < 5; q++) {
            wb[0][q][0] = Wx[q * 450 + j];
            wb[0][q][1] = Wx[q * 450 + 150 + j];
            wb[0][q][2] = Wx[q * 450 + 300 + j];
        }
#pragma unroll 2
        for (int c = 0; c < 60; c++) {
            const int cur = c & 1;
            if (c < 59) {
                int kb = (c + 1) * 5;
#pragma unroll
                for (int q = 0; q < 5; q++) {
                    wb[cur ^ 1][q][0] = Wx[(kb + q) * 450 + j];
                    wb[cur ^ 1][q][1] = Wx[(kb + q) * 450 + 150 + j];
                    wb[cur ^ 1][q][2] = Wx[(kb + q) * 450 + 300 + j];
                }
            }
            int kb = c * 5;
#pragma unroll
            for (int q = 0; q < 5; q++) {
                int k = kb + q;
                ull wi2 = pack2(wb[cur][q][0], wb[cur][q][0]);
                ull wo2 = pack2(wb[cur][q][1], wb[cur][q][1]);
                ull wu2 = pack2(wb[cur][q][2], wb[cur][q][2]);
                const ull* px = reinterpret_cast<const ull*>(&s.xs[k][0]);
#pragma unroll
                for (int p = 0; p < 8; p++) {
                    ull xv = px[p];
                    ffma2(acc[p], wi2, xv);
                    ffma2(acc[8 + p], wo2, xv);
                    ffma2(acc[16 + p], wu2, xv);
                }
            }
        }
        float bi = bx[j] + bh[j];
        float bo = bx[150 + j] + bh[150 + j];
        float bu = bx[300 + j] + bh[300 + j];
#pragma unroll
        for (int p = 0; p < 8; p++) {
            float2 fi = unpack2(acc[p]), fo = unpack2(acc[8 + p]), fu = unpack2(acc[16 + p]);
#pragma unroll
            for (int h = 0; h < 2; h++) {
                float iv = sigf((h ? fi.y : fi.x) + bi);
                float ov = sigf((h ? fo.y : fo.x) + bo);
                float uv = tanhf((h ? fu.y : fu.x) + bu);
                float c2 = iv * uv;
                g_C[t][leaf0 + 2 * p + h][j] = c2;
                g_H[t][leaf0 + 2 * p + h][j] = ov * tanhf(c2);
            }
        }
    }
    gsync(grp);
}

// ---------------------------------------------------------------------------
// Group-independent level task: 8 nodes, K=150, double-buffered weights,
// child-C prefetched into registers.
// ---------------------------------------------------------------------------
__device__ __forceinline__ void level_task_g(
    LvlG& s, int task, int e0, int P, int grp, int j,
    const int* __restrict__ lidx, const int* __restrict__ ridx,
    const float* __restrict__ Wh, const float* __restrict__ bh,
    const float* __restrict__ Wf, const float* __restrict__ bf)
{
    if (j < 8) {
        int u = task * 8 + j;
        int t = u / P;
        int e = e0 + (u - t * P);
        s.tt[j] = t; s.kk[j] = LLEAF + e;
        s.li[j] = lidx[e]; s.ri[j] = ridx[e];
    }
    gsync(grp);
    for (int idx = j; idx < 8 * MEM; idx += 160) {
        int r = idx / MEM, k = idx - r * MEM;
        float a = __ldcg(&g_H[s.tt[r]][s.li[r]][k]);
        float b = __ldcg(&g_H[s.tt[r]][s.ri[r]][k]);
        s.sl[k][r] = a; s.sr[k][r] = b; s.ss[k][r] = a + b;
    }
    gsync(grp);

    if (j < MEM) {
        float cl[8], cr[8];
#pragma unroll
        for (int r = 0; r < 8; r++) {
            cl[r] = __ldcg(&g_C[s.tt[r]][s.li[r]][j]);
            cr[r] = __ldcg(&g_C[s.tt[r]][s.ri[r]][j]);
        }
        ull acc[20];
#pragma unroll
        for (int a = 0; a < 20; a++) acc[a] = 0ull;
        float wb[2][5][4];
#pragma unroll
        for (int q = 0; q < 5; q++) {
            wb[0][q][0] = Wh[q * 450 + j];
            wb[0][q][1] = Wh[q * 450 + 150 + j];
            wb[0][q][2] = Wh[q * 450 + 300 + j];
            wb[0][q][3] = Wf[q * 150 + j];
        }
#pragma unroll 2
        for (int c = 0; c < 30; c++) {
            const int cur = c & 1;
            if (c < 29) {
                int kb = (c + 1) * 5;
#pragma unroll
                for (int q = 0; q < 5; q++) {
                    wb[cur ^ 1][q][0] = Wh[(kb + q) * 450 + j];
                    wb[cur ^ 1][q][1] = Wh[(kb + q) * 450 + 150 + j];
                    wb[cur ^ 1][q][2] = Wh[(kb + q) * 450 + 300 + j];
                    wb[cur ^ 1][q][3] = Wf[(kb + q) * 150 + j];
                }
            }
            int kb = c * 5;
#pragma unroll
            for (int q = 0; q < 5; q++) {
                int k = kb + q;
                ull wi2 = pack2(wb[cur][q][0], wb[cur][q][0]);
                ull wo2 = pack2(wb[cur][q][1], wb[cur][q][1]);
                ull wu2 = pack2(wb[cur][q][2], wb[cur][q][2]);
                ull wf2 = pack2(wb[cur][q][3], wb[cur][q][3]);
                const ull* ps = reinterpret_cast<const ull*>(&s.ss[k][0]);
                const ull* pl = reinterpret_cast<const ull*>(&s.sl[k][0]);
                const ull* pr = reinterpret_cast<const ull*>(&s.sr[k][0]);
#pragma unroll
                for (int p = 0; p < 4; p++) {
                    ull hs = ps[p];
                    ffma2(acc[p], wi2, hs);
                    ffma2(acc[4 + p], wo2, hs);
                    ffma2(acc[8 + p], wu2, hs);
                    ffma2(acc[12 + p], wf2, pl[p]);
                    ffma2(acc[16 + p], wf2, pr[p]);
                }
            }
        }
        float bi = bh[j], bo = bh[150 + j], bu = bh[300 + j], bfv = bf[j];
#pragma unroll
        for (int p = 0; p < 4; p++) {
            float2 fi = unpack2(acc[p]), fo = unpack2(acc[4 + p]), fu = unpack2(acc[8 + p]);
            float2 ffl = unpack2(acc[12 + p]), ffr = unpack2(acc[16 + p]);
#pragma unroll
            for (int h = 0; h < 2; h++) {
                int r = 2 * p + h;
                float iv = sigf((h ? fi.y : fi.x) + bi);
                float ov = sigf((h ? fo.y : fo.x) + bo);
                float uv = tanhf((h ? fu.y : fu.x) + bu);
                float fl = sigf((h ? ffl.y : ffl.x) + bfv);
                float fr = sigf((h ? ffr.y : ffr.x) + bfv);
                int t = s.tt[r];
                float c2 = iv * uv + fl * cl[r] + fr * cr[r];
                g_C[t][s.kk[r]][j] = c2;
                g_H[t][s.kk[r]][j] = ov * tanhf(c2);
            }
        }
    }
    gsync(grp);
}

// ---------------------------------------------------------------------------
// Whole-block split-K=3 level task for small levels (R in {2,4}).
// ---------------------------------------------------------------------------
template <int R>
__device__ __forceinline__ void level_task_sk(
    LvlSK& s, int task, int e0, int P, int tid, int grp, int j,
    const int* __restrict__ lidx, const int* __restrict__ ridx,
    const float* __restrict__ Wh, const float* __restrict__ bh,
    const float* __restrict__ Wf, const float* __restrict__ bf)
{
    constexpr int NP = R / 2;
    if (tid < R) {
        int u = task * R + tid;
        int t = u / P;
        int e = e0 + (u - t * P);
        s.tt[tid] = t; s.kk[tid] = LLEAF + e;
        s.li[tid] = lidx[e]; s.ri[tid] = ridx[e];
    }
    __syncthreads();
    for (int idx = tid; idx < R * MEM; idx += NTHR) {
        int r = idx / MEM, k = idx - r * MEM;
        float a = __ldcg(&g_H[s.tt[r]][s.li[r]][k]);
        float b = __ldcg(&g_H[s.tt[r]][s.ri[r]][k]);
        s.sl[k][r] = a; s.sr[k][r] = b; s.ss[k][r] = a + b;
    }
    __syncthreads();

    ull acc[5 * NP];
#pragma unroll
    for (int a = 0; a < 5 * NP; a++) acc[a] = 0ull;

    if (j < MEM) {
        const int kb = grp * 50;
        for (int kc = 0; kc < 50; kc += 5) {
            float w[5][4];
#pragma unroll
            for (int q = 0; q < 5; q++) {
                int k = kb + kc + q;
                w[q][0] = Wh[k * 450 + j];
                w[q][1] = Wh[k * 450 + 150 + j];
                w[q][2] = Wh[k * 450 + 300 + j];
                w[q][3] = Wf[k * 150 + j];
            }
#pragma unroll
            for (int q = 0; q < 5; q++) {
                int k = kb + kc + q;
                ull wi2 = pack2(w[q][0], w[q][0]);
                ull wo2 = pack2(w[q][1], w[q][1]);
                ull wu2 = pack2(w[q][2], w[q][2]);
                ull wf2 = pack2(w[q][3], w[q][3]);
                const ull* ps = reinterpret_cast<const ull*>(&s.ss[k][0]);
                const ull* pl = reinterpret_cast<const ull*>(&s.sl[k][0]);
                const ull* pr = reinterpret_cast<const ull*>(&s.sr[k][0]);
#pragma unroll
                for (int p = 0; p < NP; p++) {
                    ull hs = ps[p];
                    ffma2(acc[0 * NP + p], wi2, hs);
                    ffma2(acc[1 * NP + p], wo2, hs);
                    ffma2(acc[2 * NP + p], wu2, hs);
                    ffma2(acc[3 * NP + p], wf2, pl[p]);
                    ffma2(acc[4 * NP + p], wf2, pr[p]);
                }
            }
        }
    }

    float2 fa[5 * NP];
#pragma unroll
    for (int a = 0; a < 5 * NP; a++) fa[a] = unpack2(acc[a]);

#pragma unroll
    for (int gate = 0; gate < 5; gate++) {
        if (grp > 0 && j < MEM) {
#pragma unroll
            for (int p = 0; p < NP; p++) s.buf[grp - 1][j][p] = fa[gate * NP + p];
        }
        __syncthreads();
        if (grp == 0 && j < MEM) {
#pragma unroll
            for (int sI = 0; sI < 2; sI++)
#pragma unroll
                for (int p = 0; p < NP; p++) {
                    float2 v = s.buf[sI][j][p];
                    fa[gate * NP + p].x += v.x; fa[gate * NP + p].y += v.y;
                }
        }
        __syncthreads();
    }

    if (grp == 0 && j < MEM) {
        float bi = bh[j], bo = bh[150 + j], bu = bh[300 + j], bfv = bf[j];
#pragma unroll
        for (int p = 0; p < NP; p++) {
            float2 fi = fa[0 * NP + p], fo = fa[1 * NP + p], fu = fa[2 * NP + p];
            float2 ffl = fa[3 * NP + p], ffr = fa[4 * NP + p];
#pragma unroll
            for (int h = 0; h < 2; h++) {
                int r = 2 * p + h;
                float iv = sigf((h ? fi.y : fi.x) + bi);
                float ov = sigf((h ? fo.y : fo.x) + bo);
                float uv = tanhf((h ? fu.y : fu.x) + bu);
                float fl = sigf((h ? ffl.y : ffl.x) + bfv);
                float fr = sigf((h ? ffr.y : ffr.x) + bfv);
                int t = s.tt[r];
                float c2 = iv * uv + fl * __ldcg(&g_C[t][s.li[r]][j]) + fr * __ldcg(&g_C[t][s.ri[r]][j]);
                g_C[t][s.kk[r]][j] = c2;
                g_H[t][s.kk[r]][j] = ov * tanhf(c2);
            }
        }
    }
    __syncthreads();
}

// ---------------------------------------------------------------------------
// The whole model as one persistent kernel with grid barriers.
// ---------------------------------------------------------------------------
__global__ __launch_bounds__(NTHR, 1) void fused_kernel(
    const int* __restrict__ ltok, const int* __restrict__ rtok,
    const int* __restrict__ lidx, const int* __restrict__ ridx,
    const float* __restrict__ emb,
    const float* __restrict__ Wx, const float* __restrict__ bx,
    const float* __restrict__ Wh, const float* __restrict__ bh,
    const float* __restrict__ Wf, const float* __restrict__ bf,
    const float* __restrict__ Wa, const float* __restrict__ ba,
    const float* __restrict__ Wwh, const float* __restrict__ bwh,
    const float* __restrict__ Wwp, const float* __restrict__ bwp,
    float* __restrict__ out)
{
    extern __shared__ __align__(16) char smem_raw[];
    SmemU& sm = *reinterpret_cast<SmemU*>(smem_raw);
    const int tid = threadIdx.x;
    const int bid = blockIdx.x;
    const int grp = tid / 160;
    const int j = tid - grp * 160;
    const int G = bid * 3 + grp;                  // virtual group id
    const int NG = gridDim.x * 3;

    // ================= leaf phase: 256 group tasks =========================
    for (int task = G; task < 256; task += NG)
        leaf_task_g(sm.leafg[grp], task, grp, j, ltok, rtok, emb, Wx, bx, bh);
    gbar();

    // ================= big levels: group-independent =======================
    for (int task = G; task < 256; task += NG)    // P=1024, 256 tasks
        level_task_g(sm.lvlg[grp], task, 0, 1024, grp, j, lidx, ridx, Wh, bh, Wf, bf);
    gbar();
    for (int task = G; task < 128; task += NG)    // P=512, 128 tasks
        level_task_g(sm.lvlg[grp], task, 1024, 512, grp, j, lidx, ridx, Wh, bh, Wf, bf);
    gbar();

    // ================= small levels: whole-block split-K ===================
    for (int task = bid; task < 128; task += gridDim.x)   // P=256, R=4
        level_task_sk<4>(sm.lvlsk, task, 1536, 256, tid, grp, j, lidx, ridx, Wh, bh, Wf, bf);
    gbar();
    {
        const int e0s[8] = {1792, 1920, 1984, 2016, 2032, 2040, 2044, 2046};
        const int Ps[8]  = {128, 64, 32, 16, 8, 4, 2, 1};
        for (int lev = 0; lev < 8; lev++) {
            int P = Ps[lev];
            for (int task = bid; task < P; task += gridDim.x)
                level_task_sk<2>(sm.lvlsk, task, e0s[lev], P, tid, grp, j, lidx, ridx, Wh, bh, Wf, bf);
            gbar();
        }
    }

    // ================= attention scores ====================================
    {
        int wid = tid >> 5, lane = tid & 31;
        for (int d = bid * 15 + wid; d < 2 * NNODES; d += gridDim.x * 15) {
            int side = d / NNODES;
            int node = d - side * NNODES;
            int qt = side, rt = 1 - side;
            float sum = 0.f;
            for (int k = lane; k < MEM; k += 32)
                sum += g_H[qt][NNODES - 1][k] * g_H[rt][node][k];
#pragma unroll
            for (int off = 16; off; off >>= 1) sum += __shfl_xor_sync(0xffffffffu, sum, off);
            if (lane == 0) g_s[side][node] = sum;
        }
    }
    gbar();

    // ================= softmax normalizers (block 0) =======================
    if (bid == 0) {
        const int lane = tid & 31, w = tid >> 5;
        for (int side = 0; side < 2; side++) {
            float m = -1e30f;
            for (int i = tid; i < NNODES; i += NTHR) m = fmaxf(m, g_s[side][i]);
#pragma unroll
            for (int off = 16; off; off >>= 1) m = fmaxf(m, __shfl_xor_sync(0xffffffffu, m, off));
            if (lane == 0) sm.fin.red[w] = m;
            __syncthreads();
            if (tid == 0) {
                float mm = sm.fin.red[0];
                for (int i = 1; i < 15; i++) mm = fmaxf(mm, sm.fin.red[i]);
                sm.fin.bc = mm;
            }
            __syncthreads();
            float mx = sm.fin.bc;
            float s = 0.f;
            for (int i = tid; i < NNODES; i += NTHR) s += expf(g_s[side][i] - mx);
#pragma unroll
            for (int off = 16; off; off >>= 1) s += __shfl_xor_sync(0xffffffffu, s, off);
            __syncthreads();
            if (lane == 0) sm.fin.red[w] = s;
            __syncthreads();
            if (tid == 0) {
                float tot = 0.f;
                for (int i = 0; i < 15; i++) tot += sm.fin.red[i];
                g_red4[side * 2] = mx;
                g_red4[side * 2 + 1] = 1.f / tot;
            }
            __syncthreads();
        }
    }
    gbar();

    // ================= attention weighted sums =============================
    {
        int slot = bid * 3 + grp;              // 64 tasks: (side, chunk)
        bool active = slot < 64;
        int side = slot >> 5, chunk = slot & 31, rt = 1 - side;
        int j0 = chunk * 128;
        if (active) {
            float mx = g_red4[side * 2], inv = g_red4[side * 2 + 1];
            for (int jj = j; jj < 128; jj += 160) {
                int jg = j0 + jj;
                sm.att.w[grp][jj] = (jg < NNODES) ? expf(g_s[side][jg] - mx) * inv : 0.f;
            }
        }
        __syncthreads();
        if (active && j < MEM) {
            float p = 0.f;
            int lim = min(128, NNODES - j0);
            for (int jj = 0; jj < lim; jj++)
                p = fmaf(sm.att.w[grp][jj], g_H[rt][j0 + jj][j], p);
            g_part[side][chunk][j] = p;
        }
    }
    gbar();

    // ================= final head (block 0) ================================
    if (bid == 0) {
        if (tid < MEM) {
            sm.fin.q0[tid] = g_H[0][NNODES - 1][tid];
            sm.fin.q1[tid] = g_H[1][NNODES - 1][tid];
            float b = 0.f, a = 0.f;
            for (int p = 0; p < 32; p++) { b += g_part[0][p][tid]; a += g_part[1][p][tid]; }
            sm.fin.beta[tid] = b; sm.fin.alpha[tid] = a;
        }
        __syncthreads();
        if (tid < MEM) {
            float lh = ba[tid], rh = ba[tid];
            for (int k = 0; k < MEM; k++) {
                float w1 = Wa[k * MEM + tid];
                float w2 = Wa[(MEM + k) * MEM + tid];
                lh += sm.fin.q0[k] * w1 + sm.fin.beta[k] * w2;
                rh += sm.fin.q1[k] * w1 + sm.fin.alpha[k] * w2;
            }
            sm.fin.slh[tid] = lh; sm.fin.srh[tid] = rh;
        }
        __syncthreads();
        if (tid < HIDD) {
            float acc = bwh[tid];
            for (int k = 0; k < MEM; k++) {
                float pr = sm.fin.slh[k] * sm.fin.srh[k];
                float ad = fabsf(sm.fin.slh[k] - sm.fin.srh[k]);
                acc += pr * Wwh[k * HIDD + tid] + ad * Wwh[(MEM + k) * HIDD + tid];
            }
            sm.fin.hid[tid] = 1.f / (1.f + expf(-acc));
        }
        __syncthreads();
        if (tid < NCLS) {
            float v = bwp[tid];
            for (int m = 0; m < HIDD; m++) v += sm.fin.hid[m] * Wwp[m * NCLS + tid];
            sm.fin.lg[tid] = v;
        }
        __syncthreads();
        if (tid < NCLS) {
            float mx = sm.fin.lg[0];
            for (int c = 1; c < NCLS; c++) mx = fmaxf(mx, sm.fin.lg[c]);
            float s = 0.f;
            for (int c = 0; c < NCLS; c++) s += expf(sm.fin.lg[c] - mx);
            out[tid] = sm.fin.lg[tid] - mx - logf(s);
        }
    }
}

// ---------------------------------------------------------------------------
extern "C" void kernel_launch(void* const* d_in, const int* in_sizes, int n_in,
                              void* d_out, int out_size)
{
    const int*   ltok = (const int*)d_in[0];
    const int*   rtok = (const int*)d_in[1];
    const int*   lidx = (const int*)d_in[2];
    const int*   ridx = (const int*)d_in[3];
    const float* emb  = (const float*)d_in[4];
    const float* Wx   = (const float*)d_in[5];
    const float* bx   = (const float*)d_in[6];
    const float* Wh   = (const float*)d_in[7];
    const float* bhh  = (const float*)d_in[8];
    // d_in[9] = W_fx, d_in[10] = b_fx : unused by the reference
    const float* Wf   = (const float*)d_in[11];
    const float* bf   = (const float*)d_in[12];
    const float* Wa   = (const float*)d_in[13];
    const float* ba   = (const float*)d_in[14];
    const float* Wwh  = (const float*)d_in[15];
    const float* bwh  = (const float*)d_in[16];
    const float* Wwp  = (const float*)d_in[17];
    const float* bwp  = (const float*)d_in[18];
    float* out = (float*)d_out;

    int dev = 0, nsm = 0;
    cudaGetDevice(&dev);
    cudaDeviceGetAttribute(&nsm, cudaDevAttrMultiProcessorCount, dev);
    if (nsm <= 0) nsm = 64;   // conservative fallback, still correct

    const int smem_bytes = (int)sizeof(SmemU);
    cudaFuncSetAttribute(fused_kernel, cudaFuncAttributeMaxDynamicSharedMemorySize, smem_bytes);

    fused_kernel<<<nsm, NTHR, smem_bytes>>>(ltok, rtok, lidx, ridx, emb, Wx, bx, Wh, bhh,
                                            Wf, bf, Wa, ba, Wwh, bwh, Wwp, bwp, out);
}